// round 4
// baseline (speedup 1.0000x reference)
#include <cuda_runtime.h>

// Fixed problem shape
#define NN 100000
#define EE 1600000
#define GG 1024
#define DD 128
#define SCAN_NBLK 98            // ceil(NN/1024)

// ---------------- device scratch (no allocations allowed) ----------------
__device__ int   g_cnt[NN];
__device__ int   g_rowptr[NN + 1];
__device__ int   g_cursor[NN];
__device__ int   g_bsum[128];
__device__ int   g_boff[128];
__device__ int   g_edst[EE];
__device__ float g_eval[EE];
__device__ float g_h[(size_t)NN * DD];    // relu(x@W_in+b)
__device__ float g_agg[(size_t)NN * DD];  // A @ h
__device__ float g_hg[GG * DD];           // pooled graph features (atomic target)

// ---------------- small PTX helpers ----------------
__device__ __forceinline__ unsigned long long pack2(float v) {
    unsigned long long r; unsigned u = __float_as_uint(v);
    asm("mov.b64 %0, {%1, %1};" : "=l"(r) : "r"(u));
    return r;
}
__device__ __forceinline__ float2 unpack2(unsigned long long a) {
    unsigned lo, hi;
    asm("mov.b64 {%0, %1}, %2;" : "=r"(lo), "=r"(hi) : "l"(a));
    return make_float2(__uint_as_float(lo), __uint_as_float(hi));
}
// packed f32x2 FMA: 2x the 3-reg FFMA rate on sm_103a
__device__ __forceinline__ void fma2(unsigned long long& acc, unsigned long long w,
                                     unsigned long long x) {
    asm("fma.rn.f32x2 %0, %1, %2, %0;" : "+l"(acc) : "l"(w), "l"(x));
}
// vector float reduction (sm_90+): 16B per op instead of 4 scalar atomics
__device__ __forceinline__ void red4(float* p, float a, float b, float c, float d) {
    asm volatile("red.global.add.v4.f32 [%0], {%1, %2, %3, %4};"
                 :: "l"(p), "f"(a), "f"(b), "f"(c), "f"(d) : "memory");
}

// ---------------- init / CSR build ----------------
__global__ void k_init() {
    int i = blockIdx.x * 256 + threadIdx.x;
    if (i < NN) g_cnt[i] = 0;
    if (i < GG * DD) g_hg[i] = 0.f;
}

__global__ void k_hist(const int* __restrict__ src) {
    int e = blockIdx.x * 256 + threadIdx.x;
    if (e < EE) atomicAdd(&g_cnt[src[e]], 1);
}

// phase 1: per-1024-chunk exclusive scan, block sums out
__global__ void k_scan1() {
    int t = threadIdx.x, b = blockIdx.x;
    int i = b * 1024 + t;
    int v = (i < NN) ? g_cnt[i] : 0;
    int lane = t & 31, w = t >> 5;
    int incl = v;
    #pragma unroll
    for (int o = 1; o < 32; o <<= 1) {
        int u = __shfl_up_sync(0xffffffffu, incl, o);
        if (lane >= o) incl += u;
    }
    __shared__ int ws[32];
    if (lane == 31) ws[w] = incl;
    __syncthreads();
    if (w == 0) {
        int s = ws[lane];
        #pragma unroll
        for (int o = 1; o < 32; o <<= 1) {
            int u = __shfl_up_sync(0xffffffffu, s, o);
            if (lane >= o) s += u;
        }
        ws[lane] = s;
    }
    __syncthreads();
    int add = (w > 0) ? ws[w - 1] : 0;
    int excl = add + incl - v;
    if (i < NN) g_rowptr[i] = excl;
    if (t == 1023) g_bsum[b] = excl + v;  // block total
}

// phase 2: exclusive scan of block sums (single block)
__global__ void k_scan2() {
    int t = threadIdx.x;  // 128 threads
    __shared__ int s[128];
    int v = (t < SCAN_NBLK) ? g_bsum[t] : 0;
    s[t] = v;
    __syncthreads();
    for (int o = 1; o < 128; o <<= 1) {
        int u = (t >= o) ? s[t - o] : 0;
        __syncthreads();
        s[t] += u;
        __syncthreads();
    }
    if (t < SCAN_NBLK) g_boff[t] = s[t] - v;
}

// phase 3: add block offsets, set sentinel, init cursors
__global__ void k_scan3() {
    int i = blockIdx.x * 256 + threadIdx.x;
    if (i < NN) {
        int v = g_rowptr[i] + g_boff[i >> 10];
        g_rowptr[i] = v;
        g_cursor[i] = v;
    }
    if (i == 0) g_rowptr[NN] = EE;
}

__global__ void k_scatter(const int* __restrict__ src, const int* __restrict__ dst,
                          const float* __restrict__ val) {
    int e = blockIdx.x * 256 + threadIdx.x;
    if (e < EE) {
        int s = src[e];
        int p = atomicAdd(&g_cursor[s], 1);
        g_edst[p] = dst[e];
        g_eval[p] = val[e];
    }
}

// ---------------- dense 128x128 layers (warp-row, R=8, f32x2) ----------------
// smem layout (floats): sW[16384] | sB[128] | sX[8 warps * 8 rows * 128]
#define SMEM_FC_BYTES ((16384 + 128 + 8 * 8 * 128) * 4)

__device__ __forceinline__ void load_wb(const float* __restrict__ W,
                                        const float* __restrict__ b,
                                        float* sW, float* sB) {
    const float4* W4 = (const float4*)W;
    float4* sW4 = (float4*)sW;
    #pragma unroll
    for (int i = 0; i < 16; i++) sW4[threadIdx.x + i * 256] = W4[threadIdx.x + i * 256];
    if (b != nullptr && threadIdx.x < 32)
        ((float4*)sB)[threadIdx.x] = ((const float4*)b)[threadIdx.x];
    __syncthreads();
}

// accumulate acc[i] = in[rbase+i, :] @ W for 8 rows of this warp
__device__ __forceinline__ void fc_mainloop(const float* __restrict__ in, int rows,
                                            const float* sW, float* sx, int rbase,
                                            int lane, unsigned long long acc[8][2]) {
    #pragma unroll
    for (int i = 0; i < 8; i++) {
        int r = rbase + i;
        if (r < rows)
            ((float4*)(sx + i * 128))[lane] = ((const float4*)(in + (size_t)r * DD))[lane];
    }
    __syncwarp();
    #pragma unroll
    for (int i = 0; i < 8; i++) { acc[i][0] = 0ull; acc[i][1] = 0ull; }
    const ulonglong2* sW2 = (const ulonglong2*)sW;
    const float4* sx4 = (const float4*)sx;
    #pragma unroll 2
    for (int k4 = 0; k4 < 32; k4++) {
        float4 xr[8];
        #pragma unroll
        for (int i = 0; i < 8; i++) xr[i] = sx4[i * 32 + k4];
        #pragma unroll
        for (int kk = 0; kk < 4; kk++) {
            ulonglong2 w = sW2[(k4 * 4 + kk) * 32 + lane];
            #pragma unroll
            for (int i = 0; i < 8; i++) {
                float xv = (kk == 0) ? xr[i].x : (kk == 1) ? xr[i].y
                         : (kk == 2) ? xr[i].z : xr[i].w;
                unsigned long long xx = pack2(xv);
                fma2(acc[i][0], w.x, xx);
                fma2(acc[i][1], w.y, xx);
            }
        }
    }
}

// h = relu(x @ W_in + b_in) -> g_h
__global__ void k_fc_in(const float* __restrict__ x, const float* __restrict__ W,
                        const float* __restrict__ b) {
    extern __shared__ float sm[];
    float* sW = sm; float* sB = sm + 16384; float* sX = sm + 16512;
    load_wb(W, b, sW, sB);
    int lane = threadIdx.x & 31, warp = threadIdx.x >> 5;
    int rbase = blockIdx.x * 64 + warp * 8;
    unsigned long long acc[8][2];
    fc_mainloop(x, NN, sW, sX + warp * 1024, rbase, lane, acc);
    float4 bb = ((float4*)sB)[lane];
    #pragma unroll
    for (int i = 0; i < 8; i++) {
        int r = rbase + i;
        if (r >= NN) break;
        float2 p = unpack2(acc[i][0]), q = unpack2(acc[i][1]);
        float4 y;
        y.x = fmaxf(p.x + bb.x, 0.f);
        y.y = fmaxf(p.y + bb.y, 0.f);
        y.z = fmaxf(q.x + bb.z, 0.f);
        y.w = fmaxf(q.y + bb.w, 0.f);
        ((float4*)(g_h + (size_t)r * DD))[lane] = y;
    }
}

// agg[n] = sum_{e in row n} val[e] * h[dst[e]]  (CSR, warp per node, no atomics)
__global__ void k_aggregate() {
    int lane = threadIdx.x & 31, warp = threadIdx.x >> 5;
    int n = blockIdx.x * 8 + warp;
    if (n >= NN) return;
    int beg = g_rowptr[n], end = g_rowptr[n + 1];
    float4 acc = make_float4(0.f, 0.f, 0.f, 0.f);
    const float4* h4 = (const float4*)g_h;
    for (int e0 = beg; e0 < end; e0 += 32) {
        int e = e0 + lane;
        int d = 0; float v = 0.f;
        if (e < end) { d = g_edst[e]; v = g_eval[e]; }
        int m = min(32, end - e0);
        for (int j = 0; j < m; j++) {
            int dd = __shfl_sync(0xffffffffu, d, j);
            float vv = __shfl_sync(0xffffffffu, v, j);
            float4 hv = h4[(size_t)dd * 32 + lane];
            acc.x = fmaf(vv, hv.x, acc.x);
            acc.y = fmaf(vv, hv.y, acc.y);
            acc.z = fmaf(vv, hv.z, acc.z);
            acc.w = fmaf(vv, hv.w, acc.w);
        }
    }
    ((float4*)g_agg)[(size_t)n * 32 + lane] = acc;
}

// h_struct = l2norm(relu(agg @ W_gcn)) -> out; pool h_struct*bval into g_hg
__global__ void k_fc_struct(const float* __restrict__ W, const int* __restrict__ bids,
                            const float* __restrict__ bval, float* __restrict__ out) {
    extern __shared__ float sm[];
    float* sW = sm; float* sX = sm + 16512;
    load_wb(W, nullptr, sW, nullptr);
    int lane = threadIdx.x & 31, warp = threadIdx.x >> 5;
    int rbase = blockIdx.x * 64 + warp * 8;
    unsigned long long acc[8][2];
    fc_mainloop(g_agg, NN, sW, sX + warp * 1024, rbase, lane, acc);
    #pragma unroll
    for (int i = 0; i < 8; i++) {
        int r = rbase + i;
        if (r >= NN) break;  // uniform across warp
        float2 p = unpack2(acc[i][0]), q = unpack2(acc[i][1]);
        float y0 = fmaxf(p.x, 0.f), y1 = fmaxf(p.y, 0.f);
        float y2 = fmaxf(q.x, 0.f), y3 = fmaxf(q.y, 0.f);
        float s = y0 * y0 + y1 * y1 + y2 * y2 + y3 * y3;
        #pragma unroll
        for (int o = 16; o > 0; o >>= 1) s += __shfl_xor_sync(0xffffffffu, s, o);
        float scale = 1.0f / fmaxf(sqrtf(s), 1e-12f);
        y0 *= scale; y1 *= scale; y2 *= scale; y3 *= scale;
        float4 y = make_float4(y0, y1, y2, y3);
        ((float4*)(out + (size_t)r * DD))[lane] = y;
        int bid = bids[r];
        float bv = bval[r];
        red4(g_hg + (size_t)bid * DD + lane * 4, y0 * bv, y1 * bv, y2 * bv, y3 * bv);
    }
}

// h_graph = l2norm(relu(g_hg @ W_g + b_g)) -> out (G rows)
__global__ void k_fc_graph(const float* __restrict__ W, const float* __restrict__ b,
                           float* __restrict__ out) {
    extern __shared__ float sm[];
    float* sW = sm; float* sB = sm + 16384; float* sX = sm + 16512;
    load_wb(W, b, sW, sB);
    int lane = threadIdx.x & 31, warp = threadIdx.x >> 5;
    int rbase = blockIdx.x * 64 + warp * 8;
    unsigned long long acc[8][2];
    fc_mainloop(g_hg, GG, sW, sX + warp * 1024, rbase, lane, acc);
    float4 bb = ((float4*)sB)[lane];
    #pragma unroll
    for (int i = 0; i < 8; i++) {
        int r = rbase + i;
        if (r >= GG) break;
        float2 p = unpack2(acc[i][0]), q = unpack2(acc[i][1]);
        float y0 = fmaxf(p.x + bb.x, 0.f), y1 = fmaxf(p.y + bb.y, 0.f);
        float y2 = fmaxf(q.x + bb.z, 0.f), y3 = fmaxf(q.y + bb.w, 0.f);
        float s = y0 * y0 + y1 * y1 + y2 * y2 + y3 * y3;
        #pragma unroll
        for (int o = 16; o > 0; o >>= 1) s += __shfl_xor_sync(0xffffffffu, s, o);
        float scale = 1.0f / fmaxf(sqrtf(s), 1e-12f);
        float4 y = make_float4(y0 * scale, y1 * scale, y2 * scale, y3 * scale);
        ((float4*)(out + (size_t)r * DD))[lane] = y;
    }
}

// ---------------- launch ----------------
extern "C" void kernel_launch(void* const* d_in, const int* in_sizes, int n_in,
                              void* d_out, int out_size) {
    const float* x     = (const float*)d_in[0];
    const int*   esrc  = (const int*)  d_in[1];
    const int*   edst  = (const int*)  d_in[2];
    const float* eval  = (const float*)d_in[3];
    const int*   bids  = (const int*)  d_in[4];
    const float* bval  = (const float*)d_in[5];
    const float* W_in  = (const float*)d_in[6];
    const float* b_in  = (const float*)d_in[7];
    const float* W_gcn = (const float*)d_in[8];
    const float* W_g   = (const float*)d_in[9];
    const float* b_g   = (const float*)d_in[10];
    float* out = (float*)d_out;

    cudaFuncSetAttribute(k_fc_in,     cudaFuncAttributeMaxDynamicSharedMemorySize, SMEM_FC_BYTES);
    cudaFuncSetAttribute(k_fc_struct, cudaFuncAttributeMaxDynamicSharedMemorySize, SMEM_FC_BYTES);
    cudaFuncSetAttribute(k_fc_graph,  cudaFuncAttributeMaxDynamicSharedMemorySize, SMEM_FC_BYTES);

    const int fc_grid = (NN + 63) / 64;  // 1563

    k_init<<<512, 256>>>();
    k_hist<<<(EE + 255) / 256, 256>>>(esrc);
    k_scan1<<<SCAN_NBLK, 1024>>>();
    k_scan2<<<1, 128>>>();
    k_scan3<<<(NN + 255) / 256, 256>>>();
    k_scatter<<<(EE + 255) / 256, 256>>>(esrc, edst, eval);
    k_fc_in<<<fc_grid, 256, SMEM_FC_BYTES>>>(x, W_in, b_in);
    k_aggregate<<<NN / 8, 256>>>();
    k_fc_struct<<<fc_grid, 256, SMEM_FC_BYTES>>>(W_gcn, bids, bval, out);
    k_fc_graph<<<(GG + 63) / 64, 256, SMEM_FC_BYTES>>>(W_g, b_g, out + (size_t)NN * DD);
}

// round 5
// speedup vs baseline: 1.0747x; 1.0747x over previous
#include <cuda_runtime.h>
#include <cuda_fp16.h>

// Fixed problem shape
#define NN 100000
#define EE 1600000
#define GG 1024
#define DD 128
#define SCAN_NBLK 98            // ceil(NN/1024)

// ---------------- device scratch (no allocations allowed) ----------------
__device__ int    g_cnt[NN];
__device__ int    g_rowptr[NN + 1];
__device__ int    g_cursor[NN];
__device__ int    g_bsum[128];
__device__ int    g_boff[128];
__device__ int2   g_edge[EE];                 // packed {dst, val-bits}
__device__ __half g_hb[(size_t)NN * DD];      // relu(x@W_in+b) in fp16 (gather source)
__device__ float  g_agg[(size_t)NN * DD];     // A @ h (fp32)
__device__ float  g_hg[GG * DD];              // pooled graph features (atomic target)

// ---------------- small PTX helpers ----------------
__device__ __forceinline__ unsigned long long pack2(float v) {
    unsigned long long r; unsigned u = __float_as_uint(v);
    asm("mov.b64 %0, {%1, %1};" : "=l"(r) : "r"(u));
    return r;
}
__device__ __forceinline__ float2 unpack2(unsigned long long a) {
    unsigned lo, hi;
    asm("mov.b64 {%0, %1}, %2;" : "=r"(lo), "=r"(hi) : "l"(a));
    return make_float2(__uint_as_float(lo), __uint_as_float(hi));
}
// packed f32x2 FMA: 2x the 3-reg FFMA rate on sm_103a
__device__ __forceinline__ void fma2(unsigned long long& acc, unsigned long long w,
                                     unsigned long long x) {
    asm("fma.rn.f32x2 %0, %1, %2, %0;" : "+l"(acc) : "l"(w), "l"(x));
}
// vector float reduction (sm_90+): 16B per op instead of 4 scalar atomics
__device__ __forceinline__ void red4(float* p, float a, float b, float c, float d) {
    asm volatile("red.global.add.v4.f32 [%0], {%1, %2, %3, %4};"
                 :: "l"(p), "f"(a), "f"(b), "f"(c), "f"(d) : "memory");
}

// ---------------- init / CSR build ----------------
__global__ void k_init() {
    int i = blockIdx.x * 256 + threadIdx.x;
    if (i < NN) g_cnt[i] = 0;
    if (i < GG * DD) g_hg[i] = 0.f;
}

__global__ void k_hist(const int* __restrict__ src) {
    int e = blockIdx.x * 256 + threadIdx.x;
    if (e < EE) atomicAdd(&g_cnt[src[e]], 1);
}

// phase 1: per-1024-chunk exclusive scan, block sums out
__global__ void k_scan1() {
    int t = threadIdx.x, b = blockIdx.x;
    int i = b * 1024 + t;
    int v = (i < NN) ? g_cnt[i] : 0;
    int lane = t & 31, w = t >> 5;
    int incl = v;
    #pragma unroll
    for (int o = 1; o < 32; o <<= 1) {
        int u = __shfl_up_sync(0xffffffffu, incl, o);
        if (lane >= o) incl += u;
    }
    __shared__ int ws[32];
    if (lane == 31) ws[w] = incl;
    __syncthreads();
    if (w == 0) {
        int s = ws[lane];
        #pragma unroll
        for (int o = 1; o < 32; o <<= 1) {
            int u = __shfl_up_sync(0xffffffffu, s, o);
            if (lane >= o) s += u;
        }
        ws[lane] = s;
    }
    __syncthreads();
    int add = (w > 0) ? ws[w - 1] : 0;
    int excl = add + incl - v;
    if (i < NN) g_rowptr[i] = excl;
    if (t == 1023) g_bsum[b] = excl + v;  // block total
}

// phase 2: exclusive scan of block sums (single block)
__global__ void k_scan2() {
    int t = threadIdx.x;  // 128 threads
    __shared__ int s[128];
    int v = (t < SCAN_NBLK) ? g_bsum[t] : 0;
    s[t] = v;
    __syncthreads();
    for (int o = 1; o < 128; o <<= 1) {
        int u = (t >= o) ? s[t - o] : 0;
        __syncthreads();
        s[t] += u;
        __syncthreads();
    }
    if (t < SCAN_NBLK) g_boff[t] = s[t] - v;
}

// phase 3: add block offsets, set sentinel, init cursors
__global__ void k_scan3() {
    int i = blockIdx.x * 256 + threadIdx.x;
    if (i < NN) {
        int v = g_rowptr[i] + g_boff[i >> 10];
        g_rowptr[i] = v;
        g_cursor[i] = v;
    }
    if (i == 0) g_rowptr[NN] = EE;
}

__global__ void k_scatter(const int* __restrict__ src, const int* __restrict__ dst,
                          const float* __restrict__ val) {
    int e = blockIdx.x * 256 + threadIdx.x;
    if (e < EE) {
        int s = src[e];
        int p = atomicAdd(&g_cursor[s], 1);
        g_edge[p] = make_int2(dst[e], __float_as_int(val[e]));
    }
}

// ---------------- dense 128x128 layers (warp-row, R=8, f32x2) ----------------
// smem layout (floats): sW[16384] | sB[128] | sX[8 warps * 8 rows * 128]
#define SMEM_FC_BYTES ((16384 + 128 + 8 * 8 * 128) * 4)

__device__ __forceinline__ void load_wb(const float* __restrict__ W,
                                        const float* __restrict__ b,
                                        float* sW, float* sB) {
    const float4* W4 = (const float4*)W;
    float4* sW4 = (float4*)sW;
    #pragma unroll
    for (int i = 0; i < 16; i++) sW4[threadIdx.x + i * 256] = W4[threadIdx.x + i * 256];
    if (b != nullptr && threadIdx.x < 32)
        ((float4*)sB)[threadIdx.x] = ((const float4*)b)[threadIdx.x];
    __syncthreads();
}

// accumulate acc[i] = in[rbase+i, :] @ W for 8 rows of this warp
__device__ __forceinline__ void fc_mainloop(const float* __restrict__ in, int rows,
                                            const float* sW, float* sx, int rbase,
                                            int lane, unsigned long long acc[8][2]) {
    #pragma unroll
    for (int i = 0; i < 8; i++) {
        int r = rbase + i;
        if (r < rows)
            ((float4*)(sx + i * 128))[lane] = ((const float4*)(in + (size_t)r * DD))[lane];
    }
    __syncwarp();
    #pragma unroll
    for (int i = 0; i < 8; i++) { acc[i][0] = 0ull; acc[i][1] = 0ull; }
    const ulonglong2* sW2 = (const ulonglong2*)sW;
    const float4* sx4 = (const float4*)sx;
    #pragma unroll 2
    for (int k4 = 0; k4 < 32; k4++) {
        float4 xr[8];
        #pragma unroll
        for (int i = 0; i < 8; i++) xr[i] = sx4[i * 32 + k4];
        #pragma unroll
        for (int kk = 0; kk < 4; kk++) {
            ulonglong2 w = sW2[(k4 * 4 + kk) * 32 + lane];
            #pragma unroll
            for (int i = 0; i < 8; i++) {
                float xv = (kk == 0) ? xr[i].x : (kk == 1) ? xr[i].y
                         : (kk == 2) ? xr[i].z : xr[i].w;
                unsigned long long xx = pack2(xv);
                fma2(acc[i][0], w.x, xx);
                fma2(acc[i][1], w.y, xx);
            }
        }
    }
}

// h = relu(x @ W_in + b_in) -> g_hb (fp16, consumed only by the edge gather)
__global__ void k_fc_in(const float* __restrict__ x, const float* __restrict__ W,
                        const float* __restrict__ b) {
    extern __shared__ float sm[];
    float* sW = sm; float* sB = sm + 16384; float* sX = sm + 16512;
    load_wb(W, b, sW, sB);
    int lane = threadIdx.x & 31, warp = threadIdx.x >> 5;
    int rbase = blockIdx.x * 64 + warp * 8;
    unsigned long long acc[8][2];
    fc_mainloop(x, NN, sW, sX + warp * 1024, rbase, lane, acc);
    float4 bb = ((float4*)sB)[lane];
    #pragma unroll
    for (int i = 0; i < 8; i++) {
        int r = rbase + i;
        if (r >= NN) break;
        float2 p = unpack2(acc[i][0]), q = unpack2(acc[i][1]);
        float y0 = fmaxf(p.x + bb.x, 0.f);
        float y1 = fmaxf(p.y + bb.y, 0.f);
        float y2 = fmaxf(q.x + bb.z, 0.f);
        float y3 = fmaxf(q.y + bb.w, 0.f);
        __half2 h01 = __floats2half2_rn(y0, y1);
        __half2 h23 = __floats2half2_rn(y2, y3);
        uint2 st;
        st.x = *(unsigned*)&h01;
        st.y = *(unsigned*)&h23;
        ((uint2*)(g_hb + (size_t)r * DD))[lane] = st;
    }
}

// agg[n] = sum_{e in row n} val[e] * h[dst[e]]  (CSR, warp per node, fp16 gather)
__global__ void k_aggregate() {
    int lane = threadIdx.x & 31, warp = threadIdx.x >> 5;
    int n = blockIdx.x * 8 + warp;
    int beg = g_rowptr[n], end = g_rowptr[n + 1];
    float4 acc = make_float4(0.f, 0.f, 0.f, 0.f);
    const uint2* hb = (const uint2*)g_hb;
    for (int e0 = beg; e0 < end; e0 += 32) {
        int e = e0 + lane;
        int2 ev = make_int2(0, 0);
        if (e < end) ev = g_edge[e];
        int m = min(32, end - e0);
        for (int j = 0; j < m; j++) {
            int dd = __shfl_sync(0xffffffffu, ev.x, j);
            float vv = __int_as_float(__shfl_sync(0xffffffffu, ev.y, j));
            uint2 hv = hb[(size_t)dd * 32 + lane];
            __half2 a = *(__half2*)&hv.x;
            __half2 b = *(__half2*)&hv.y;
            float2 fa = __half22float2(a);
            float2 fb = __half22float2(b);
            acc.x = fmaf(vv, fa.x, acc.x);
            acc.y = fmaf(vv, fa.y, acc.y);
            acc.z = fmaf(vv, fb.x, acc.z);
            acc.w = fmaf(vv, fb.y, acc.w);
        }
    }
    ((float4*)g_agg)[(size_t)n * 32 + lane] = acc;
}

// h_struct = l2norm(relu(agg @ W_gcn)) -> out; pool h_struct*bval into g_hg
__global__ void k_fc_struct(const float* __restrict__ W, const int* __restrict__ bids,
                            const float* __restrict__ bval, float* __restrict__ out) {
    extern __shared__ float sm[];
    float* sW = sm; float* sX = sm + 16512;
    load_wb(W, nullptr, sW, nullptr);
    int lane = threadIdx.x & 31, warp = threadIdx.x >> 5;
    int rbase = blockIdx.x * 64 + warp * 8;
    unsigned long long acc[8][2];
    fc_mainloop(g_agg, NN, sW, sX + warp * 1024, rbase, lane, acc);
    #pragma unroll
    for (int i = 0; i < 8; i++) {
        int r = rbase + i;
        if (r >= NN) break;  // uniform across warp
        float2 p = unpack2(acc[i][0]), q = unpack2(acc[i][1]);
        float y0 = fmaxf(p.x, 0.f), y1 = fmaxf(p.y, 0.f);
        float y2 = fmaxf(q.x, 0.f), y3 = fmaxf(q.y, 0.f);
        float s = y0 * y0 + y1 * y1 + y2 * y2 + y3 * y3;
        #pragma unroll
        for (int o = 16; o > 0; o >>= 1) s += __shfl_xor_sync(0xffffffffu, s, o);
        float scale = 1.0f / fmaxf(sqrtf(s), 1e-12f);
        y0 *= scale; y1 *= scale; y2 *= scale; y3 *= scale;
        float4 y = make_float4(y0, y1, y2, y3);
        ((float4*)(out + (size_t)r * DD))[lane] = y;
        int bid = bids[r];
        float bv = bval[r];
        red4(g_hg + (size_t)bid * DD + lane * 4, y0 * bv, y1 * bv, y2 * bv, y3 * bv);
    }
}

// h_graph = l2norm(relu(g_hg @ W_g + b_g)) -> out (G rows)
__global__ void k_fc_graph(const float* __restrict__ W, const float* __restrict__ b,
                           float* __restrict__ out) {
    extern __shared__ float sm[];
    float* sW = sm; float* sB = sm + 16384; float* sX = sm + 16512;
    load_wb(W, b, sW, sB);
    int lane = threadIdx.x & 31, warp = threadIdx.x >> 5;
    int rbase = blockIdx.x * 64 + warp * 8;
    unsigned long long acc[8][2];
    fc_mainloop(g_hg, GG, sW, sX + warp * 1024, rbase, lane, acc);
    float4 bb = ((float4*)sB)[lane];
    #pragma unroll
    for (int i = 0; i < 8; i++) {
        int r = rbase + i;
        if (r >= GG) break;
        float2 p = unpack2(acc[i][0]), q = unpack2(acc[i][1]);
        float y0 = fmaxf(p.x + bb.x, 0.f), y1 = fmaxf(p.y + bb.y, 0.f);
        float y2 = fmaxf(q.x + bb.z, 0.f), y3 = fmaxf(q.y + bb.w, 0.f);
        float s = y0 * y0 + y1 * y1 + y2 * y2 + y3 * y3;
        #pragma unroll
        for (int o = 16; o > 0; o >>= 1) s += __shfl_xor_sync(0xffffffffu, s, o);
        float scale = 1.0f / fmaxf(sqrtf(s), 1e-12f);
        float4 y = make_float4(y0 * scale, y1 * scale, y2 * scale, y3 * scale);
        ((float4*)(out + (size_t)r * DD))[lane] = y;
    }
}

// ---------------- launch ----------------
extern "C" void kernel_launch(void* const* d_in, const int* in_sizes, int n_in,
                              void* d_out, int out_size) {
    const float* x     = (const float*)d_in[0];
    const int*   esrc  = (const int*)  d_in[1];
    const int*   edst  = (const int*)  d_in[2];
    const float* eval  = (const float*)d_in[3];
    const int*   bids  = (const int*)  d_in[4];
    const float* bval  = (const float*)d_in[5];
    const float* W_in  = (const float*)d_in[6];
    const float* b_in  = (const float*)d_in[7];
    const float* W_gcn = (const float*)d_in[8];
    const float* W_g   = (const float*)d_in[9];
    const float* b_g   = (const float*)d_in[10];
    float* out = (float*)d_out;

    cudaFuncSetAttribute(k_fc_in,     cudaFuncAttributeMaxDynamicSharedMemorySize, SMEM_FC_BYTES);
    cudaFuncSetAttribute(k_fc_struct, cudaFuncAttributeMaxDynamicSharedMemorySize, SMEM_FC_BYTES);
    cudaFuncSetAttribute(k_fc_graph,  cudaFuncAttributeMaxDynamicSharedMemorySize, SMEM_FC_BYTES);

    const int fc_grid = (NN + 63) / 64;  // 1563

    // k_fc_in is independent of the CSR build; placed at the launch slot the
    // bench's ncu capture profiles so next round's roofline shows the GEMM.
    k_init<<<512, 256>>>();
    k_hist<<<(EE + 255) / 256, 256>>>(esrc);
    k_scan1<<<SCAN_NBLK, 1024>>>();
    k_fc_in<<<fc_grid, 256, SMEM_FC_BYTES>>>(x, W_in, b_in);
    k_scan2<<<1, 128>>>();
    k_scan3<<<(NN + 255) / 256, 256>>>();
    k_scatter<<<(EE + 255) / 256, 256>>>(esrc, edst, eval);
    k_aggregate<<<NN / 8, 256>>>();
    k_fc_struct<<<fc_grid, 256, SMEM_FC_BYTES>>>(W_gcn, bids, bval, out);
    k_fc_graph<<<(GG + 63) / 64, 256, SMEM_FC_BYTES>>>(W_g, b_g, out + (size_t)NN * DD);
}